// round 4
// baseline (speedup 1.0000x reference)
#include <cuda_runtime.h>
#include <cstdint>
#include <cstdio>

#define D 128
#define MAXN 50000
#define LDA 132   // padded lead dim (floats) for conflict-free mma fragment loads

// Scratch (device globals: allocation-free contract). 16B-aligned for vector ld/st.
__device__ __align__(16) float g_PQR[(size_t)MAXN * 384];  // [N][384]: P=h@W1a^T, Q=h@W1b^T, R=h@U1a^T
__device__ __align__(16) float g_agg[(size_t)MAXN * D];    // scatter-add target
__device__ int g_oddor;                                     // OR of odd 32-bit words of edge buffer

__device__ __forceinline__ unsigned f2tf(float x){
    unsigned u; asm("cvt.rna.tf32.f32 %0, %1;" : "=r"(u) : "f"(x)); return u;
}
__device__ __forceinline__ float silu(float x){
    return x * (1.0f / (1.0f + __expf(-x)));
}
__device__ __forceinline__ void mma8(float* c, const unsigned* a, const unsigned* b){
    asm volatile(
      "mma.sync.aligned.m16n8k8.row.col.f32.tf32.tf32.f32 "
      "{%0,%1,%2,%3},{%4,%5,%6,%7},{%8,%9},{%0,%1,%2,%3};\n"
      : "+f"(c[0]), "+f"(c[1]), "+f"(c[2]), "+f"(c[3])
      : "r"(a[0]), "r"(a[1]), "r"(a[2]), "r"(a[3]), "r"(b[0]), "r"(b[1]));
}

// ---------------------------------------------------------------------------
// Probe: detect edge_index element width. If the buffer holds int64 values
// < 2^31, every odd 32-bit word (hi-word, little-endian) is 0. If it holds
// int32 indices, odd words are random node ids -> OR is nonzero.
// ---------------------------------------------------------------------------
__global__ void probe_kernel(const int* __restrict__ ebuf)
{
    int v = 0;
    for (int i = threadIdx.x; i < 4096; i += blockDim.x)
        v |= ebuf[2 * i + 1];
    // warp + block reduce via atomic (g_oddor zeroed by memset before launch)
    if (v) atomicOr(&g_oddor, v);
}

// ---------------------------------------------------------------------------
// Kernel 1: PQR = h @ Wcat^T  (Wcat rows: 0..127 W1[:, :128], 128..255 W1[:,128:256], 256..383 U1[:, :128])
// Tile: 32 rows x 384 cols, 8 warps (each warp 48 cols), K=128.
// ---------------------------------------------------------------------------
__global__ __launch_bounds__(256) void gemm1_kernel(
    const float* __restrict__ h, const float* __restrict__ W1,
    const float* __restrict__ U1, int N)
{
    extern __shared__ unsigned sm[];
    unsigned* sW = sm;               // 384*LDA
    unsigned* sA = sm + 384 * LDA;   // 32*LDA
    int tid = threadIdx.x;

    for (int idx = tid; idx < 384 * D; idx += 256) {
        int r = idx >> 7, k = idx & 127;
        float v;
        if (r < 128)      v = W1[r * 257 + k];
        else if (r < 256) v = W1[(r - 128) * 257 + 128 + k];
        else              v = U1[(r - 256) * 256 + k];
        sW[r * LDA + k] = f2tf(v);
    }

    int w = tid >> 5, l = tid & 31, g = l >> 2, t4 = l & 3;
    int nbase = w * 48;
    int ntiles = (N + 31) >> 5;

    for (int tt = blockIdx.x; tt < ntiles; tt += gridDim.x) {
        __syncthreads();
        int row0 = tt << 5;
        for (int idx = tid; idx < 32 * D; idx += 256) {
            int r = idx >> 7, k = idx & 127;
            int i = row0 + r;
            float v = (i < N) ? h[(size_t)i * D + k] : 0.0f;
            sA[r * LDA + k] = f2tf(v);
        }
        __syncthreads();

        float acc[2][6][4];
        #pragma unroll
        for (int mf = 0; mf < 2; mf++)
            #pragma unroll
            for (int nf = 0; nf < 6; nf++)
                #pragma unroll
                for (int q = 0; q < 4; q++) acc[mf][nf][q] = 0.f;

        #pragma unroll
        for (int ks = 0; ks < 16; ++ks) {
            int kb = ks * 8;
            unsigned a[2][4];
            #pragma unroll
            for (int mf = 0; mf < 2; mf++) {
                int r0 = mf * 16 + g;
                a[mf][0] = sA[r0 * LDA + kb + t4];
                a[mf][1] = sA[(r0 + 8) * LDA + kb + t4];
                a[mf][2] = sA[r0 * LDA + kb + t4 + 4];
                a[mf][3] = sA[(r0 + 8) * LDA + kb + t4 + 4];
            }
            #pragma unroll
            for (int nf = 0; nf < 6; nf++) {
                unsigned b[2];
                int n = nbase + nf * 8 + g;
                b[0] = sW[n * LDA + kb + t4];
                b[1] = sW[n * LDA + kb + t4 + 4];
                mma8(acc[0][nf], a[0], b);
                mma8(acc[1][nf], a[1], b);
            }
        }
        #pragma unroll
        for (int mf = 0; mf < 2; mf++) {
            int i0 = row0 + mf * 16 + g;
            int i1 = i0 + 8;
            #pragma unroll
            for (int nf = 0; nf < 6; nf++) {
                int col = nbase + nf * 8 + t4 * 2;
                if (i0 < N) *(float2*)&g_PQR[(size_t)i0 * 384 + col] = make_float2(acc[mf][nf][0], acc[mf][nf][1]);
                if (i1 < N) *(float2*)&g_PQR[(size_t)i1 * 384 + col] = make_float2(acc[mf][nf][2], acc[mf][nf][3]);
            }
        }
    }
}

// ---------------------------------------------------------------------------
// Kernel 2: edge kernel. Tile = 64 edges.
//   t   = silu(P[s] + Q[r] + dist*w1c + b1)     [64 x 128]
//   m   = silu(t @ W2^T + b2)                   [64 x 128]
//   atomicAdd agg[recv] += m
// 8 warps: 4 row-groups (16 edges) x 2 col-groups (64 outs).
// ---------------------------------------------------------------------------
__global__ __launch_bounds__(256, 2) void edge_kernel(
    const float* __restrict__ coords, const void* __restrict__ eraw,
    const float* __restrict__ W1, const float* __restrict__ b1,
    const float* __restrict__ W2, const float* __restrict__ b2,
    int N, int E)
{
    extern __shared__ unsigned sm[];
    unsigned* sW2 = sm;               // 128*LDA
    unsigned* sT  = sm + 128 * LDA;   // 64*LDA
    float* sb1   = (float*)(sT + 64 * LDA);
    float* sb2   = sb1 + 128;
    float* swc   = sb2 + 128;
    float* sDist = swc + 128;
    int*   sS    = (int*)(sDist + 64);
    int*   sR    = sS + 64;
    int tid = threadIdx.x;

    const bool is64 = (g_oddor == 0);
    const int*       e32 = (const int*)eraw;
    const long long* e64 = (const long long*)eraw;

    for (int idx = tid; idx < 128 * D; idx += 256) {
        int o = idx >> 7, k = idx & 127;
        sW2[o * LDA + k] = f2tf(W2[o * D + k]);
    }
    if (tid < 128) { sb1[tid] = b1[tid]; sb2[tid] = b2[tid]; swc[tid] = W1[tid * 257 + 256]; }

    int w = tid >> 5, l = tid & 31, g = l >> 2, t4 = l & 3;
    int wr = w >> 1, wc = w & 1;
    int ntiles = (E + 63) >> 6;

    for (int tt = blockIdx.x; tt < ntiles; tt += gridDim.x) {
        __syncthreads();
        int e0 = tt << 6;
        if (tid < 64) {
            int e = e0 + tid;
            int s = 0, r = 0; float dd = 0.f;
            if (e < E) {
                if (is64) { s = (int)e64[e]; r = (int)e64[(size_t)E + e]; }
                else      { s = e32[e];      r = e32[(size_t)E + e]; }
                // defensive clamp (indices must be in [0,N))
                if ((unsigned)s >= (unsigned)N) s = 0;
                if ((unsigned)r >= (unsigned)N) r = 0;
                float dx = coords[s * 3 + 0] - coords[r * 3 + 0];
                float dy = coords[s * 3 + 1] - coords[r * 3 + 1];
                float dz = coords[s * 3 + 2] - coords[r * 3 + 2];
                dd = sqrtf(dx * dx + dy * dy + dz * dz);
            }
            sS[tid] = s; sR[tid] = r; sDist[tid] = dd;
        }
        __syncthreads();

        // build t tile: 2048 float4-quads, each thread handles 8 (edge row e, quad oc)
        #pragma unroll
        for (int half = 0; half < 2; ++half) {
            float4 pv[4], qv[4]; float dv[4]; int el[4], ocl[4];
            #pragma unroll
            for (int it = 0; it < 4; ++it) {
                int idx = tid + (half * 4 + it) * 256;
                int e = idx >> 5, oc = idx & 31;
                el[it] = e; ocl[it] = oc;
                int s = sS[e], r = sR[e];
                pv[it] = *(const float4*)&g_PQR[(size_t)s * 384 + oc * 4];
                qv[it] = *(const float4*)&g_PQR[(size_t)r * 384 + 128 + oc * 4];
                dv[it] = sDist[e];
            }
            #pragma unroll
            for (int it = 0; it < 4; ++it) {
                int e = el[it], c = ocl[it] * 4;
                float x0 = pv[it].x + qv[it].x + dv[it] * swc[c + 0] + sb1[c + 0];
                float x1 = pv[it].y + qv[it].y + dv[it] * swc[c + 1] + sb1[c + 1];
                float x2 = pv[it].z + qv[it].z + dv[it] * swc[c + 2] + sb1[c + 2];
                float x3 = pv[it].w + qv[it].w + dv[it] * swc[c + 3] + sb1[c + 3];
                uint4 st = make_uint4(f2tf(silu(x0)), f2tf(silu(x1)), f2tf(silu(x2)), f2tf(silu(x3)));
                *(uint4*)&sT[e * LDA + c] = st;
            }
        }
        __syncthreads();

        float acc[8][4];
        #pragma unroll
        for (int nf = 0; nf < 8; nf++)
            #pragma unroll
            for (int q = 0; q < 4; q++) acc[nf][q] = 0.f;

        #pragma unroll
        for (int ks = 0; ks < 16; ++ks) {
            int kb = ks * 8;
            unsigned a[4];
            int r0 = wr * 16 + g;
            a[0] = sT[r0 * LDA + kb + t4];
            a[1] = sT[(r0 + 8) * LDA + kb + t4];
            a[2] = sT[r0 * LDA + kb + t4 + 4];
            a[3] = sT[(r0 + 8) * LDA + kb + t4 + 4];
            #pragma unroll
            for (int nf = 0; nf < 8; nf++) {
                unsigned b[2];
                int n = wc * 64 + nf * 8 + g;
                b[0] = sW2[n * LDA + kb + t4];
                b[1] = sW2[n * LDA + kb + t4 + 4];
                mma8(acc[nf], a, b);
            }
        }

        int rA = wr * 16 + g;
        int recA = sR[rA], recB = sR[rA + 8];
        bool vA = (e0 + rA) < E, vB = (e0 + rA + 8) < E;
        #pragma unroll
        for (int nf = 0; nf < 8; nf++) {
            int col = wc * 64 + nf * 8 + t4 * 2;
            float m0 = silu(acc[nf][0] + sb2[col]);
            float m1 = silu(acc[nf][1] + sb2[col + 1]);
            float m2 = silu(acc[nf][2] + sb2[col]);
            float m3 = silu(acc[nf][3] + sb2[col + 1]);
            if (vA) { atomicAdd(&g_agg[(size_t)recA * D + col], m0); atomicAdd(&g_agg[(size_t)recA * D + col + 1], m1); }
            if (vB) { atomicAdd(&g_agg[(size_t)recB * D + col], m2); atomicAdd(&g_agg[(size_t)recB * D + col + 1], m3); }
        }
    }
}

// ---------------------------------------------------------------------------
// Kernel 3: node update. Tile = 64 nodes.
//   t   = silu(agg @ U1b^T + R + c1)
//   out = h + t @ U2^T + c2
// sW rows 0..127 = U1b (U1[:,128:256]), rows 128..255 = U2.
// ---------------------------------------------------------------------------
__global__ __launch_bounds__(256) void node_kernel(
    const float* __restrict__ h, const float* __restrict__ U1,
    const float* __restrict__ U2, const float* __restrict__ c1,
    const float* __restrict__ c2, float* __restrict__ out, int N)
{
    extern __shared__ unsigned sm[];
    unsigned* sW = sm;               // 256*LDA
    unsigned* sA = sm + 256 * LDA;   // 64*LDA (agg tile, then reused as t tile)
    float* sc1 = (float*)(sA + 64 * LDA);
    float* sc2 = sc1 + 128;
    int tid = threadIdx.x;

    for (int idx = tid; idx < 256 * D; idx += 256) {
        int r = idx >> 7, k = idx & 127;
        float v = (r < 128) ? U1[r * 256 + 128 + k] : U2[(r - 128) * D + k];
        sW[r * LDA + k] = f2tf(v);
    }
    if (tid < 128) { sc1[tid] = c1[tid]; sc2[tid] = c2[tid]; }

    int w = tid >> 5, l = tid & 31, g = l >> 2, t4 = l & 3;
    int wr = w >> 1, wc = w & 1;
    int ntiles = (N + 63) >> 6;

    for (int tt = blockIdx.x; tt < ntiles; tt += gridDim.x) {
        __syncthreads();
        int n0 = tt << 6;
        for (int idx = tid; idx < 64 * D; idx += 256) {
            int r = idx >> 7, k = idx & 127;
            int i = n0 + r;
            float v = (i < N) ? g_agg[(size_t)i * D + k] : 0.f;
            sA[r * LDA + k] = f2tf(v);
        }
        __syncthreads();

        float acc[8][4];
        #pragma unroll
        for (int nf = 0; nf < 8; nf++)
            #pragma unroll
            for (int q = 0; q < 4; q++) acc[nf][q] = 0.f;

        #pragma unroll
        for (int ks = 0; ks < 16; ++ks) {
            int kb = ks * 8;
            unsigned a[4];
            int r0 = wr * 16 + g;
            a[0] = sA[r0 * LDA + kb + t4];
            a[1] = sA[(r0 + 8) * LDA + kb + t4];
            a[2] = sA[r0 * LDA + kb + t4 + 4];
            a[3] = sA[(r0 + 8) * LDA + kb + t4 + 4];
            #pragma unroll
            for (int nf = 0; nf < 8; nf++) {
                unsigned b[2];
                int n = wc * 64 + nf * 8 + g;
                b[0] = sW[n * LDA + kb + t4];
                b[1] = sW[n * LDA + kb + t4 + 4];
                mma8(acc[nf], a, b);
            }
        }
        __syncthreads();  // all warps done reading agg tile before overwrite with t

        int rA = wr * 16 + g;
        int i0 = n0 + rA, i1 = i0 + 8;
        #pragma unroll
        for (int nf = 0; nf < 8; nf++) {
            int col = wc * 64 + nf * 8 + t4 * 2;
            float r00 = 0.f, r01 = 0.f, r10 = 0.f, r11 = 0.f;
            if (i0 < N) { float2 rv = *(const float2*)&g_PQR[(size_t)i0 * 384 + 256 + col]; r00 = rv.x; r01 = rv.y; }
            if (i1 < N) { float2 rv = *(const float2*)&g_PQR[(size_t)i1 * 384 + 256 + col]; r10 = rv.x; r11 = rv.y; }
            sA[rA * LDA + col]           = f2tf(silu(acc[nf][0] + r00 + sc1[col]));
            sA[rA * LDA + col + 1]       = f2tf(silu(acc[nf][1] + r01 + sc1[col + 1]));
            sA[(rA + 8) * LDA + col]     = f2tf(silu(acc[nf][2] + r10 + sc1[col]));
            sA[(rA + 8) * LDA + col + 1] = f2tf(silu(acc[nf][3] + r11 + sc1[col + 1]));
        }
        __syncthreads();

        float acc2[8][4];
        #pragma unroll
        for (int nf = 0; nf < 8; nf++)
            #pragma unroll
            for (int q = 0; q < 4; q++) acc2[nf][q] = 0.f;

        #pragma unroll
        for (int ks = 0; ks < 16; ++ks) {
            int kb = ks * 8;
            unsigned a[4];
            int r0 = wr * 16 + g;
            a[0] = sA[r0 * LDA + kb + t4];
            a[1] = sA[(r0 + 8) * LDA + kb + t4];
            a[2] = sA[r0 * LDA + kb + t4 + 4];
            a[3] = sA[(r0 + 8) * LDA + kb + t4 + 4];
            #pragma unroll
            for (int nf = 0; nf < 8; nf++) {
                unsigned b[2];
                int n = 128 + wc * 64 + nf * 8 + g;
                b[0] = sW[n * LDA + kb + t4];
                b[1] = sW[n * LDA + kb + t4 + 4];
                mma8(acc2[nf], a, b);
            }
        }

        #pragma unroll
        for (int nf = 0; nf < 8; nf++) {
            int col = wc * 64 + nf * 8 + t4 * 2;
            if (i0 < N) {
                float2 hv = *(const float2*)&h[(size_t)i0 * D + col];
                *(float2*)&out[(size_t)i0 * D + col] =
                    make_float2(hv.x + acc2[nf][0] + sc2[col], hv.y + acc2[nf][1] + sc2[col + 1]);
            }
            if (i1 < N) {
                float2 hv = *(const float2*)&h[(size_t)i1 * D + col];
                *(float2*)&out[(size_t)i1 * D + col] =
                    make_float2(hv.x + acc2[nf][2] + sc2[col], hv.y + acc2[nf][3] + sc2[col + 1]);
            }
        }
    }
}

// ---------------------------------------------------------------------------
extern "C" void kernel_launch(void* const* d_in, const int* in_sizes, int n_in,
                              void* d_out, int out_size)
{
    const float* h      = (const float*)d_in[0];
    const float* coords = (const float*)d_in[1];
    const void*  eraw   = (const void*)d_in[2];
    const float* W1     = (const float*)d_in[3];
    const float* b1     = (const float*)d_in[4];
    const float* W2     = (const float*)d_in[5];
    const float* b2     = (const float*)d_in[6];
    const float* U1     = (const float*)d_in[7];
    const float* c1     = (const float*)d_in[8];
    const float* U2     = (const float*)d_in[9];
    const float* c2     = (const float*)d_in[10];

    int N = in_sizes[0] / D;
    int E = in_sizes[2] / 2;
    if (N > MAXN) N = MAXN;

    const int SMEM1 = (384 * LDA + 32 * LDA) * 4;                       // 219,648
    const int SMEM2 = (128 * LDA + 64 * LDA) * 4 + (3 * 128 + 64) * 4 + 2 * 64 * 4;  // 103,680
    const int SMEM3 = (256 * LDA + 64 * LDA) * 4 + 2 * 128 * 4;         // 169,984

    cudaFuncSetAttribute(gemm1_kernel, cudaFuncAttributeMaxDynamicSharedMemorySize, SMEM1);
    cudaFuncSetAttribute(edge_kernel,  cudaFuncAttributeMaxDynamicSharedMemorySize, SMEM2);
    cudaFuncSetAttribute(node_kernel,  cudaFuncAttributeMaxDynamicSharedMemorySize, SMEM3);

    void* aggPtr = nullptr;
    cudaGetSymbolAddress(&aggPtr, g_agg);
    cudaMemsetAsync(aggPtr, 0, (size_t)N * D * sizeof(float));
    void* flagPtr = nullptr;
    cudaGetSymbolAddress(&flagPtr, g_oddor);
    cudaMemsetAsync(flagPtr, 0, sizeof(int));

    probe_kernel<<<1, 256>>>((const int*)eraw);
    gemm1_kernel<<<152, 256, SMEM1>>>(h, W1, U1, N);
    edge_kernel<<<304, 256, SMEM2>>>(coords, eraw, W1, b1, W2, b2, N, E);
    node_kernel<<<152, 256, SMEM3>>>(h, U1, U2, c1, c2, (float*)d_out, N);
}

// round 5
// speedup vs baseline: 1.0850x; 1.0850x over previous
#include <cuda_runtime.h>
#include <cstdint>
#include <cstdio>

#define D 128
#define MAXN 50000
#define LDA 132   // padded lead dim (floats) for conflict-free mma fragment loads

// Scratch (device globals: allocation-free contract). 16B-aligned for vector ld/st.
__device__ __align__(16) float g_PQR[(size_t)MAXN * 384];  // [N][384]: P=h@W1a^T, Q=h@W1b^T, R=h@U1a^T
__device__ __align__(16) float g_agg[(size_t)MAXN * D];    // scatter-add target
__device__ int g_oddor;                                     // OR of odd 32-bit words of edge buffer

__device__ __forceinline__ unsigned f2tf(float x){
    unsigned u; asm("cvt.rna.tf32.f32 %0, %1;" : "=r"(u) : "f"(x)); return u;
}
__device__ __forceinline__ float silu(float x){
    return x * (1.0f / (1.0f + __expf(-x)));
}
__device__ __forceinline__ void mma8(float* c, const unsigned* a, const unsigned* b){
    asm volatile(
      "mma.sync.aligned.m16n8k8.row.col.f32.tf32.tf32.f32 "
      "{%0,%1,%2,%3},{%4,%5,%6,%7},{%8,%9},{%0,%1,%2,%3};\n"
      : "+f"(c[0]), "+f"(c[1]), "+f"(c[2]), "+f"(c[3])
      : "r"(a[0]), "r"(a[1]), "r"(a[2]), "r"(a[3]), "r"(b[0]), "r"(b[1]));
}
__device__ __forceinline__ void red2(float* addr, float x, float y){
    asm volatile("red.global.add.v2.f32 [%0], {%1,%2};" :: "l"(addr), "f"(x), "f"(y) : "memory");
}

// ---------------------------------------------------------------------------
// Probe: detect edge_index element width (int64 hi-words all zero vs int32).
// ---------------------------------------------------------------------------
__global__ void probe_kernel(const int* __restrict__ ebuf)
{
    int v = 0;
    for (int i = threadIdx.x; i < 4096; i += blockDim.x)
        v |= ebuf[2 * i + 1];
    if (v) atomicOr(&g_oddor, v);
}

// ---------------------------------------------------------------------------
// Kernel 1: PQR = h @ Wcat^T. 512 threads, tile 32 rows x 384 cols.
// 16 warps: each warp 24 cols (3 nf), 2 m-fragments.
// ---------------------------------------------------------------------------
__global__ __launch_bounds__(512) void gemm1_kernel(
    const float* __restrict__ h, const float* __restrict__ W1,
    const float* __restrict__ U1, int N)
{
    extern __shared__ unsigned sm[];
    unsigned* sW = sm;               // 384*LDA
    unsigned* sA = sm + 384 * LDA;   // 32*LDA
    int tid = threadIdx.x;

    for (int idx = tid; idx < 384 * D; idx += 512) {
        int r = idx >> 7, k = idx & 127;
        float v;
        if (r < 128)      v = W1[r * 257 + k];
        else if (r < 256) v = W1[(r - 128) * 257 + 128 + k];
        else              v = U1[(r - 256) * 256 + k];
        sW[r * LDA + k] = f2tf(v);
    }

    int w = tid >> 5, l = tid & 31, g = l >> 2, t4 = l & 3;
    int nbase = w * 24;
    int ntiles = (N + 31) >> 5;

    for (int tt = blockIdx.x; tt < ntiles; tt += gridDim.x) {
        __syncthreads();
        int row0 = tt << 5;
        // vectorized tile load: 32 rows x 32 quads = 1024 quads
        #pragma unroll
        for (int it = 0; it < 2; ++it) {
            int idx = tid + it * 512;
            int r = idx >> 5, q = idx & 31;
            int i = row0 + r;
            float4 v = make_float4(0.f, 0.f, 0.f, 0.f);
            if (i < N) v = *(const float4*)&h[(size_t)i * D + q * 4];
            uint4 u = make_uint4(f2tf(v.x), f2tf(v.y), f2tf(v.z), f2tf(v.w));
            *(uint4*)&sA[r * LDA + q * 4] = u;
        }
        __syncthreads();

        float acc[2][3][4];
        #pragma unroll
        for (int mf = 0; mf < 2; mf++)
            #pragma unroll
            for (int nf = 0; nf < 3; nf++)
                #pragma unroll
                for (int q = 0; q < 4; q++) acc[mf][nf][q] = 0.f;

        #pragma unroll
        for (int ks = 0; ks < 16; ++ks) {
            int kb = ks * 8;
            unsigned a[2][4];
            #pragma unroll
            for (int mf = 0; mf < 2; mf++) {
                int r0 = mf * 16 + g;
                a[mf][0] = sA[r0 * LDA + kb + t4];
                a[mf][1] = sA[(r0 + 8) * LDA + kb + t4];
                a[mf][2] = sA[r0 * LDA + kb + t4 + 4];
                a[mf][3] = sA[(r0 + 8) * LDA + kb + t4 + 4];
            }
            #pragma unroll
            for (int nf = 0; nf < 3; nf++) {
                unsigned b[2];
                int n = nbase + nf * 8 + g;
                b[0] = sW[n * LDA + kb + t4];
                b[1] = sW[n * LDA + kb + t4 + 4];
                mma8(acc[0][nf], a[0], b);
                mma8(acc[1][nf], a[1], b);
            }
        }
        #pragma unroll
        for (int mf = 0; mf < 2; mf++) {
            int i0 = row0 + mf * 16 + g;
            int i1 = i0 + 8;
            #pragma unroll
            for (int nf = 0; nf < 3; nf++) {
                int col = nbase + nf * 8 + t4 * 2;
                if (i0 < N) *(float2*)&g_PQR[(size_t)i0 * 384 + col] = make_float2(acc[mf][nf][0], acc[mf][nf][1]);
                if (i1 < N) *(float2*)&g_PQR[(size_t)i1 * 384 + col] = make_float2(acc[mf][nf][2], acc[mf][nf][3]);
            }
        }
    }
}

// ---------------------------------------------------------------------------
// Kernel 2: edge kernel. Tile = 64 edges. 256 threads, 2 CTAs/SM.
//   t = silu(P[s]+Q[r]+dist*w1c+b1); m = silu(t@W2^T+b2); row-contig red.v2 scatter.
// ---------------------------------------------------------------------------
__global__ __launch_bounds__(256, 2) void edge_kernel(
    const float* __restrict__ coords, const void* __restrict__ eraw,
    const float* __restrict__ W1, const float* __restrict__ b1,
    const float* __restrict__ W2, const float* __restrict__ b2,
    int N, int E)
{
    extern __shared__ unsigned sm[];
    unsigned* sW2 = sm;               // 128*LDA
    unsigned* sT  = sm + 128 * LDA;   // 64*LDA  (t tile, then reused for m tile)
    float* sb1   = (float*)(sT + 64 * LDA);
    float* sb2   = sb1 + 128;
    float* swc   = sb2 + 128;
    float* sDist = swc + 128;
    int*   sS    = (int*)(sDist + 64);
    int*   sR    = sS + 64;
    int tid = threadIdx.x;

    const bool is64 = (g_oddor == 0);
    const int*       e32 = (const int*)eraw;
    const long long* e64 = (const long long*)eraw;

    // vectorized W2 load: 128 rows x 32 quads
    #pragma unroll
    for (int it = 0; it < 16; ++it) {
        int idx = tid + it * 256;
        int o = idx >> 5, q = idx & 31;
        float4 v = *(const float4*)&W2[o * D + q * 4];
        uint4 u = make_uint4(f2tf(v.x), f2tf(v.y), f2tf(v.z), f2tf(v.w));
        *(uint4*)&sW2[o * LDA + q * 4] = u;
    }
    if (tid < 128) { sb1[tid] = b1[tid]; sb2[tid] = b2[tid]; swc[tid] = W1[tid * 257 + 256]; }

    int w = tid >> 5, l = tid & 31, g = l >> 2, t4 = l & 3;
    int wr = w >> 1, wc = w & 1;
    int ntiles = (E + 63) >> 6;

    for (int tt = blockIdx.x; tt < ntiles; tt += gridDim.x) {
        __syncthreads();
        int e0 = tt << 6;
        if (tid < 64) {
            int e = e0 + tid;
            int s = 0, r = 0; float dd = 0.f;
            if (e < E) {
                if (is64) { s = (int)e64[e]; r = (int)e64[(size_t)E + e]; }
                else      { s = e32[e];      r = e32[(size_t)E + e]; }
                if ((unsigned)s >= (unsigned)N) s = 0;
                if ((unsigned)r >= (unsigned)N) r = 0;
                float dx = coords[s * 3 + 0] - coords[r * 3 + 0];
                float dy = coords[s * 3 + 1] - coords[r * 3 + 1];
                float dz = coords[s * 3 + 2] - coords[r * 3 + 2];
                dd = sqrtf(dx * dx + dy * dy + dz * dz);
            }
            sS[tid] = s; sR[tid] = r; sDist[tid] = dd;
        }
        __syncthreads();

        // build t tile: 2048 float4-quads
        #pragma unroll
        for (int half = 0; half < 2; ++half) {
            float4 pv[4], qv[4]; float dv[4]; int el[4], ocl[4];
            #pragma unroll
            for (int it = 0; it < 4; ++it) {
                int idx = tid + (half * 4 + it) * 256;
                int e = idx >> 5, oc = idx & 31;
                el[it] = e; ocl[it] = oc;
                int s = sS[e], r = sR[e];
                pv[it] = *(const float4*)&g_PQR[(size_t)s * 384 + oc * 4];
                qv[it] = *(const float4*)&g_PQR[(size_t)r * 384 + 128 + oc * 4];
                dv[it] = sDist[e];
            }
            #pragma unroll
            for (int it = 0; it < 4; ++it) {
                int e = el[it], c = ocl[it] * 4;
                float x0 = pv[it].x + qv[it].x + dv[it] * swc[c + 0] + sb1[c + 0];
                float x1 = pv[it].y + qv[it].y + dv[it] * swc[c + 1] + sb1[c + 1];
                float x2 = pv[it].z + qv[it].z + dv[it] * swc[c + 2] + sb1[c + 2];
                float x3 = pv[it].w + qv[it].w + dv[it] * swc[c + 3] + sb1[c + 3];
                uint4 st = make_uint4(f2tf(silu(x0)), f2tf(silu(x1)), f2tf(silu(x2)), f2tf(silu(x3)));
                *(uint4*)&sT[e * LDA + c] = st;
            }
        }
        __syncthreads();

        float acc[8][4];
        #pragma unroll
        for (int nf = 0; nf < 8; nf++)
            #pragma unroll
            for (int q = 0; q < 4; q++) acc[nf][q] = 0.f;

        #pragma unroll
        for (int ks = 0; ks < 16; ++ks) {
            int kb = ks * 8;
            unsigned a[4];
            int r0 = wr * 16 + g;
            a[0] = sT[r0 * LDA + kb + t4];
            a[1] = sT[(r0 + 8) * LDA + kb + t4];
            a[2] = sT[r0 * LDA + kb + t4 + 4];
            a[3] = sT[(r0 + 8) * LDA + kb + t4 + 4];
            #pragma unroll
            for (int nf = 0; nf < 8; nf++) {
                unsigned b[2];
                int n = wc * 64 + nf * 8 + g;
                b[0] = sW2[n * LDA + kb + t4];
                b[1] = sW2[n * LDA + kb + t4 + 4];
                mma8(acc[nf], a, b);
            }
        }
        __syncthreads();   // all mma reads of sT done before m overwrite

        // write m tile into sT (rows wr*16+g / +8, cols wc*64..)
        int rA = wr * 16 + g;
        #pragma unroll
        for (int nf = 0; nf < 8; nf++) {
            int col = wc * 64 + nf * 8 + t4 * 2;
            sT[rA * LDA + col]           = __float_as_uint(silu(acc[nf][0] + sb2[col]));
            sT[rA * LDA + col + 1]       = __float_as_uint(silu(acc[nf][1] + sb2[col + 1]));
            sT[(rA + 8) * LDA + col]     = __float_as_uint(silu(acc[nf][2] + sb2[col]));
            sT[(rA + 8) * LDA + col + 1] = __float_as_uint(silu(acc[nf][3] + sb2[col + 1]));
        }
        __syncthreads();

        // scatter: each warp handles one row per j; 32 lanes cover the 512B row
        #pragma unroll
        for (int j = 0; j < 8; ++j) {
            int e = w + j * 8;
            if (e0 + e < E) {
                float4 v = *(const float4*)&sT[e * LDA + l * 4];
                float* dst = &g_agg[(size_t)sR[e] * D + l * 4];
                red2(dst, v.x, v.y);
                red2(dst + 2, v.z, v.w);
            }
        }
    }
}

// ---------------------------------------------------------------------------
// Kernel 3: node update. 512 threads, tile 128 nodes.
//   t = silu(agg @ U1b^T + R + c1);  out = h + t @ U2^T + c2
// 16 warps: 8 row-groups (16 nodes) x 2 col-groups (64 outs).
// ---------------------------------------------------------------------------
__global__ __launch_bounds__(512) void node_kernel(
    const float* __restrict__ h, const float* __restrict__ U1,
    const float* __restrict__ U2, const float* __restrict__ c1,
    const float* __restrict__ c2, float* __restrict__ out, int N)
{
    extern __shared__ unsigned sm[];
    unsigned* sW = sm;               // 256*LDA (U1b rows 0..127, U2 rows 128..255)
    unsigned* sA = sm + 256 * LDA;   // 128*LDA (agg tile, then t tile)
    float* sc1 = (float*)(sA + 128 * LDA);
    float* sc2 = sc1 + 128;
    int tid = threadIdx.x;

    // vectorized weight load: 256 rows x 32 quads = 8192 quads
    #pragma unroll
    for (int it = 0; it < 16; ++it) {
        int idx = tid + it * 512;
        int r = idx >> 5, q = idx & 31;
        float4 v;
        if (r < 128) v = *(const float4*)&U1[r * 256 + 128 + q * 4];
        else         v = *(const float4*)&U2[(r - 128) * D + q * 4];
        uint4 u = make_uint4(f2tf(v.x), f2tf(v.y), f2tf(v.z), f2tf(v.w));
        *(uint4*)&sW[r * LDA + q * 4] = u;
    }
    if (tid < 128) { sc1[tid] = c1[tid]; sc2[tid] = c2[tid]; }

    int w = tid >> 5, l = tid & 31, g = l >> 2, t4 = l & 3;
    int wr = w >> 1, wc = w & 1;
    int ntiles = (N + 127) >> 7;

    for (int tt = blockIdx.x; tt < ntiles; tt += gridDim.x) {
        __syncthreads();
        int n0 = tt << 7;
        // vectorized agg tile load: 128 rows x 32 quads = 4096 quads
        #pragma unroll
        for (int it = 0; it < 8; ++it) {
            int idx = tid + it * 512;
            int r = idx >> 5, q = idx & 31;
            int i = n0 + r;
            float4 v = make_float4(0.f, 0.f, 0.f, 0.f);
            if (i < N) v = *(const float4*)&g_agg[(size_t)i * D + q * 4];
            uint4 u = make_uint4(f2tf(v.x), f2tf(v.y), f2tf(v.z), f2tf(v.w));
            *(uint4*)&sA[r * LDA + q * 4] = u;
        }
        __syncthreads();

        float acc[8][4];
        #pragma unroll
        for (int nf = 0; nf < 8; nf++)
            #pragma unroll
            for (int q = 0; q < 4; q++) acc[nf][q] = 0.f;

        #pragma unroll
        for (int ks = 0; ks < 16; ++ks) {
            int kb = ks * 8;
            unsigned a[4];
            int r0 = wr * 16 + g;
            a[0] = sA[r0 * LDA + kb + t4];
            a[1] = sA[(r0 + 8) * LDA + kb + t4];
            a[2] = sA[r0 * LDA + kb + t4 + 4];
            a[3] = sA[(r0 + 8) * LDA + kb + t4 + 4];
            #pragma unroll
            for (int nf = 0; nf < 8; nf++) {
                unsigned b[2];
                int n = wc * 64 + nf * 8 + g;
                b[0] = sW[n * LDA + kb + t4];
                b[1] = sW[n * LDA + kb + t4 + 4];
                mma8(acc[nf], a, b);
            }
        }
        __syncthreads();  // all warps done reading agg tile before overwrite with t

        int rA = wr * 16 + g;
        int i0 = n0 + rA, i1 = i0 + 8;
        #pragma unroll
        for (int nf = 0; nf < 8; nf++) {
            int col = wc * 64 + nf * 8 + t4 * 2;
            float r00 = 0.f, r01 = 0.f, r10 = 0.f, r11 = 0.f;
            if (i0 < N) { float2 rv = *(const float2*)&g_PQR[(size_t)i0 * 384 + 256 + col]; r00 = rv.x; r01 = rv.y; }
            if (i1 < N) { float2 rv = *(const float2*)&g_PQR[(size_t)i1 * 384 + 256 + col]; r10 = rv.x; r11 = rv.y; }
            sA[rA * LDA + col]           = f2tf(silu(acc[nf][0] + r00 + sc1[col]));
            sA[rA * LDA + col + 1]       = f2tf(silu(acc[nf][1] + r01 + sc1[col + 1]));
            sA[(rA + 8) * LDA + col]     = f2tf(silu(acc[nf][2] + r10 + sc1[col]));
            sA[(rA + 8) * LDA + col + 1] = f2tf(silu(acc[nf][3] + r11 + sc1[col + 1]));
        }
        __syncthreads();

        float acc2[8][4];
        #pragma unroll
        for (int nf = 0; nf < 8; nf++)
            #pragma unroll
            for (int q = 0; q < 4; q++) acc2[nf][q] = 0.f;

        #pragma unroll
        for (int ks = 0; ks < 16; ++ks) {
            int kb = ks * 8;
            unsigned a[4];
            int r0 = wr * 16 + g;
            a[0] = sA[r0 * LDA + kb + t4];
            a[1] = sA[(r0 + 8) * LDA + kb + t4];
            a[2] = sA[r0 * LDA + kb + t4 + 4];
            a[3] = sA[(r0 + 8) * LDA + kb + t4 + 4];
            #pragma unroll
            for (int nf = 0; nf < 8; nf++) {
                unsigned b[2];
                int n = 128 + wc * 64 + nf * 8 + g;
                b[0] = sW[n * LDA + kb + t4];
                b[1] = sW[n * LDA + kb + t4 + 4];
                mma8(acc2[nf], a, b);
            }
        }

        #pragma unroll
        for (int nf = 0; nf < 8; nf++) {
            int col = wc * 64 + nf * 8 + t4 * 2;
            if (i0 < N) {
                float2 hv = *(const float2*)&h[(size_t)i0 * D + col];
                *(float2*)&out[(size_t)i0 * D + col] =
                    make_float2(hv.x + acc2[nf][0] + sc2[col], hv.y + acc2[nf][1] + sc2[col + 1]);
            }
            if (i1 < N) {
                float2 hv = *(const float2*)&h[(size_t)i1 * D + col];
                *(float2*)&out[(size_t)i1 * D + col] =
                    make_float2(hv.x + acc2[nf][2] + sc2[col], hv.y + acc2[nf][3] + sc2[col + 1]);
            }
        }
    }
}

// ---------------------------------------------------------------------------
extern "C" void kernel_launch(void* const* d_in, const int* in_sizes, int n_in,
                              void* d_out, int out_size)
{
    const float* h      = (const float*)d_in[0];
    const float* coords = (const float*)d_in[1];
    const void*  eraw   = (const void*)d_in[2];
    const float* W1     = (const float*)d_in[3];
    const float* b1     = (const float*)d_in[4];
    const float* W2     = (const float*)d_in[5];
    const float* b2     = (const float*)d_in[6];
    const float* U1     = (const float*)d_in[7];
    const float* c1     = (const float*)d_in[8];
    const float* U2     = (const float*)d_in[9];
    const float* c2     = (const float*)d_in[10];

    int N = in_sizes[0] / D;
    int E = in_sizes[2] / 2;
    if (N > MAXN) N = MAXN;

    const int SMEM1 = (384 * LDA + 32 * LDA) * 4;                                    // 219,648
    const int SMEM2 = (128 * LDA + 64 * LDA) * 4 + (3 * 128 + 64) * 4 + 2 * 64 * 4;  // 103,680
    const int SMEM3 = (256 * LDA + 128 * LDA) * 4 + 2 * 128 * 4;                     // 203,776

    cudaFuncSetAttribute(gemm1_kernel, cudaFuncAttributeMaxDynamicSharedMemorySize, SMEM1);
    cudaFuncSetAttribute(edge_kernel,  cudaFuncAttributeMaxDynamicSharedMemorySize, SMEM2);
    cudaFuncSetAttribute(node_kernel,  cudaFuncAttributeMaxDynamicSharedMemorySize, SMEM3);

    void* aggPtr = nullptr;
    cudaGetSymbolAddress(&aggPtr, g_agg);
    cudaMemsetAsync(aggPtr, 0, (size_t)N * D * sizeof(float));
    void* flagPtr = nullptr;
    cudaGetSymbolAddress(&flagPtr, g_oddor);
    cudaMemsetAsync(flagPtr, 0, sizeof(int));

    probe_kernel<<<1, 256>>>((const int*)eraw);
    gemm1_kernel<<<152, 512, SMEM1>>>(h, W1, U1, N);
    edge_kernel<<<304, 256, SMEM2>>>(coords, eraw, W1, b1, W2, b2, N, E);
    node_kernel<<<152, 512, SMEM3>>>(h, U1, U2, c1, c2, (float*)d_out, N);
}